// round 2
// baseline (speedup 1.0000x reference)
#include <cuda_runtime.h>
#include <cuda_bf16.h>
#include <math.h>
#include <stdint.h>

#define T_  2048
#define E_  400
#define NS  20480
#define NK  384
#define NA  128
#define NP  (NK*NA)
#define KG  1220
#define LDH 152

__device__ float d_embeds[T_ * E_];
__device__ float d_Xbuf[2 * T_ * 800];
__device__ float d_states[T_ * 400];
__device__ float d_attns[T_];
__device__ float d_g[(size_t)NS * KG];
__device__ float d_prod[(size_t)NP * KG];
__device__ float d_h1[(size_t)NP * LDH];
__device__ float d_h2[(size_t)NP * LDH];
__device__ float d_si[NS];
__device__ int   d_keep[NK];
__device__ float d_sk[NK];
__device__ int   d_stk[NK];
__device__ int   d_enk[NK];
__device__ float d_gk[NK * KG];
__device__ float d_Ai[NK * 150];
__device__ float d_Bj[NK * 150];
__device__ float d_Dd[9 * 150];
__device__ float d_ps[NP];

__device__ __forceinline__ int binfn(int x) {
  return (x>=1)+(x>=2)+(x>=3)+(x>=4)+(x>=8)+(x>=16)+(x>=32)+(x>=64);
}
__device__ __forceinline__ uint32_t s2u(const void* p) {
  uint32_t a; asm("{ .reg .u64 t; cvta.to.shared.u64 t, %1; cvt.u32.u64 %0, t; }" : "=r"(a) : "l"(p));
  return a;
}
__device__ __forceinline__ void st_cluster(uint32_t laddr, uint32_t rank, float v) {
  asm volatile("{ .reg .b32 ra; mapa.shared::cluster.u32 ra, %0, %1; st.shared::cluster.f32 [ra], %2; }"
               :: "r"(laddr), "r"(rank), "f"(v) : "memory");
}
__device__ __forceinline__ void csync() {
  asm volatile("barrier.cluster.arrive.aligned;" ::: "memory");
  asm volatile("barrier.cluster.wait.aligned;" ::: "memory");
}

// ---------------- embedding gather ----------------
__global__ void k_embed(const int* __restrict__ tok, const float* __restrict__ emb) {
  int t = blockIdx.x; int row = tok[t];
  const float4* s = (const float4*)(emb + (size_t)row * E_);
  float4* d = (float4*)(d_embeds + (size_t)t * E_);
  for (int i = threadIdx.x; i < E_/4; i += blockDim.x) d[i] = s[i];
}

// ---------------- generic SGEMM: C = act(A@W^T + bias) ----------------
__global__ void k_gemm(const float* __restrict__ A, const float* __restrict__ W,
                       const float* __restrict__ bias, float* __restrict__ C,
                       int M, int N, int K, int lda, int wstride, int ldc, int relu)
{
  __shared__ __align__(16) float As[32][68];
  __shared__ float Ws[32][161];
  int tid = threadIdx.x, tx = tid & 15, ty = tid >> 4;
  int row0 = blockIdx.x * 64, col0 = blockIdx.y * 160;
  float acc[4][10];
#pragma unroll
  for (int i=0;i<4;i++)
#pragma unroll
    for (int j=0;j<10;j++) acc[i][j]=0.f;

  for (int k0 = 0; k0 < K; k0 += 32) {
    int ks = K - k0; if (ks > 32) ks = 32;
#pragma unroll
    for (int it = 0; it < 2; it++) {
      int idx = tid + it*256, m = idx>>3, q = idx&7;
      float4 v = make_float4(0.f,0.f,0.f,0.f);
      int rg = row0 + m;
      if (rg < M && q*4 < ks) v = *(const float4*)(A + (size_t)rg*lda + k0 + q*4);
      As[q*4+0][m]=v.x; As[q*4+1][m]=v.y; As[q*4+2][m]=v.z; As[q*4+3][m]=v.w;
    }
    for (int idx = tid; idx < 160*32; idx += 256) {
      int n = idx>>5, k = idx&31, ng = col0 + n;
      Ws[k][n] = (ng < N && k < ks) ? W[(size_t)ng*wstride + k0 + k] : 0.f;
    }
    __syncthreads();
#pragma unroll
    for (int k = 0; k < 32; k++) {
      float4 a4 = *(const float4*)(&As[k][ty*4]);
      float a[4] = {a4.x, a4.y, a4.z, a4.w};
      float w[10];
#pragma unroll
      for (int j=0;j<10;j++) w[j] = Ws[k][tx*10+j];
#pragma unroll
      for (int i=0;i<4;i++)
#pragma unroll
        for (int j=0;j<10;j++) acc[i][j] += a[i]*w[j];
    }
    __syncthreads();
  }
#pragma unroll
  for (int i=0;i<4;i++) {
    int rg = row0 + ty*4 + i; if (rg >= M) continue;
#pragma unroll
    for (int j=0;j<10;j++) {
      int ng = col0 + tx*10 + j; if (ng >= N) continue;
      float v = acc[i][j];
      if (bias) v += bias[ng];
      if (relu) v = v > 0.f ? v : 0.f;
      C[(size_t)rg*ldc + ng] = v;
    }
  }
}

// ---------------- LSTM recurrence: cluster of 4 CTAs per direction ----------------
__global__ void __launch_bounds__(400,1) k_lstm(const float* __restrict__ whhf,
                                                const float* __restrict__ whhb)
{
  int rank = blockIdx.x & 3, dir = blockIdx.x >> 2;
  const float* whh = dir ? whhb : whhf;
  const float* X = d_Xbuf + (size_t)dir * T_ * 800;
  int tid = threadIdx.x, gid = tid >> 1, half = tid & 1;
  int q = gid / 50, tloc = gid % 50;
  int grow = q*200 + rank*50 + tloc;           // global gate row
  float w[100];
  const float* wr = whh + (size_t)grow*200 + half*100;
#pragma unroll
  for (int j=0;j<100;j++) w[j] = wr[j];
  __shared__ __align__(16) float hbuf[2][208];
  __shared__ float gbuf[200];
  if (tid < 200) hbuf[0][tid] = 0.f;
  float c = 0.f;
  __syncthreads();
  csync();
  int p = 0;
  for (int s = 0; s < T_; s++) {
    int tt = dir ? (T_-1-s) : s;
    float acc = 0.f;
#pragma unroll
    for (int k4 = 0; k4 < 25; k4++) {
      float4 h4 = *(const float4*)(&hbuf[p][half*100 + k4*4]);
      acc += w[k4*4+0]*h4.x + w[k4*4+1]*h4.y + w[k4*4+2]*h4.z + w[k4*4+3]*h4.w;
    }
    unsigned m = __activemask();
    acc += __shfl_xor_sync(m, acc, 1);
    if (half == 0) gbuf[gid] = acc + X[(size_t)tt*800 + grow];
    __syncthreads();
    if (tid < 50) {
      float ig = 1.f/(1.f+expf(-gbuf[tid]));
      float fg = 1.f/(1.f+expf(-gbuf[50+tid]));
      float gg = tanhf(gbuf[100+tid]);
      float og = 1.f/(1.f+expf(-gbuf[150+tid]));
      c = fg*c + ig*gg;
      float h = og * tanhf(c);
      int tg = rank*50 + tid;
      d_states[(size_t)tt*400 + dir*200 + tg] = h;
      uint32_t la = s2u(&hbuf[1-p][tg]);
#pragma unroll
      for (int pe = 0; pe < 4; pe++) st_cluster(la, pe, h);
    }
    csync();
    p ^= 1;
  }
}

// ---------------- per-row dot: out[r] = h2[r]·w3 + b3 ----------------
__global__ void k_dot3(const float* __restrict__ h2, const float* __restrict__ w3,
                       const float* __restrict__ b3, float* __restrict__ out, int M, int lda)
{
  int row = blockIdx.x*8 + (threadIdx.x>>5), lane = threadIdx.x & 31;
  if (row >= M) return;
  const float* hp = h2 + (size_t)row*lda;
  float pSum = 0.f;
  for (int k = lane; k < 150; k += 32) pSum += hp[k]*w3[k];
#pragma unroll
  for (int o = 16; o > 0; o >>= 1) pSum += __shfl_down_sync(0xffffffffu, pSum, o);
  if (lane == 0) out[row] = pSum + b3[0];
}

// ---------------- span feature build ----------------
__global__ void k_spang(const int* __restrict__ ss, const int* __restrict__ se,
                        const float* __restrict__ wemb)
{
  int sp = blockIdx.x, st = ss[sp], en = se[sp], width = en - st + 1;
  __shared__ float aw[10];
  int tid = threadIdx.x;
  if (tid < 10) {
    int ix = st + tid; if (ix > T_-1) ix = T_-1;
    aw[tid] = (tid < width) ? d_attns[ix] : -1e9f;
  }
  __syncthreads();
  float mx = aw[0];
#pragma unroll
  for (int w2 = 1; w2 < 10; w2++) mx = fmaxf(mx, aw[w2]);
  float wt[10], ssum = 0.f;
#pragma unroll
  for (int w2 = 0; w2 < 10; w2++) { float e = expf(aw[w2]-mx); wt[w2]=e; ssum+=e; }
  float inv = 1.f/ssum;
  float* grow = d_g + (size_t)sp*KG;
  for (int e = tid; e < 400; e += blockDim.x) {
    grow[e]     = d_states[(size_t)st*400 + e];
    grow[400+e] = d_states[(size_t)en*400 + e];
    float acc = 0.f;
#pragma unroll
    for (int w2 = 0; w2 < 10; w2++) {
      int ix = st + w2; if (ix > T_-1) ix = T_-1;
      acc += wt[w2] * d_embeds[(size_t)ix*E_ + e];
    }
    grow[800+e] = acc * inv;
  }
  if (tid < 20) grow[1200+tid] = wemb[binfn(width)*20 + tid];
}

// ---------------- exact top-k + positional stable sort ----------------
__global__ void __launch_bounds__(1024) k_topk(const int* __restrict__ ss, const int* __restrict__ se)
{
  int tid = threadIdx.x;
  unsigned long long key[20];
#pragma unroll
  for (int i = 0; i < 20; i++) {
    int idx = i*1024 + tid;
    unsigned u = __float_as_uint(d_si[idx]);
    u = (u & 0x80000000u) ? ~u : (u | 0x80000000u);
    key[i] = ((unsigned long long)u << 32) | (unsigned long long)(0xFFFFFFFFu - (unsigned)idx);
  }
  __shared__ int cnt, selc;
  __shared__ unsigned long long sel[512], sel2[512];
  unsigned long long lo = 0ull, hi = ~0ull;
  while (lo < hi) {
    unsigned long long mid = lo + ((hi-lo)>>1) + 1ull;
    if (tid == 0) cnt = 0;
    __syncthreads();
    int c = 0;
#pragma unroll
    for (int i = 0; i < 20; i++) c += (key[i] >= mid);
#pragma unroll
    for (int o = 16; o > 0; o >>= 1) c += __shfl_down_sync(0xffffffffu, c, o);
    if ((tid&31)==0) atomicAdd(&cnt, c);
    __syncthreads();
    int total = cnt;
    __syncthreads();
    if (total >= NK) lo = mid; else hi = mid - 1ull;
  }
  if (tid == 0) selc = 0;
  __syncthreads();
#pragma unroll
  for (int i = 0; i < 20; i++)
    if (key[i] >= lo) { int pp = atomicAdd(&selc, 1); if (pp < 512) sel[pp] = key[i]; }
  __syncthreads();
  if (tid < 512 && tid >= selc) sel[tid] = 0ull;
  __syncthreads();
  for (int ksz = 2; ksz <= 512; ksz <<= 1)
    for (int jsz = ksz>>1; jsz > 0; jsz >>= 1) {
      if (tid < 512) {
        int ixj = tid ^ jsz;
        if (ixj > tid) {
          bool asc = ((tid & ksz) == 0);
          unsigned long long a = sel[tid], b = sel[ixj];
          if ((a > b) == asc) { sel[tid]=b; sel[ixj]=a; }
        }
      }
      __syncthreads();
    }
  if (tid < 512) {
    if (tid < NK) {
      unsigned long long kk = sel[511 - tid];
      unsigned idx = 0xFFFFFFFFu - (unsigned)(kk & 0xFFFFFFFFull);
      unsigned st = (unsigned)ss[idx], en = (unsigned)se[idx];
      unsigned long long pos = (unsigned long long)(st*2049u + en);
      sel2[tid] = (pos << 24) | ((unsigned long long)tid << 15) | (unsigned long long)idx;
    } else sel2[tid] = ~0ull;
  }
  __syncthreads();
  for (int ksz = 2; ksz <= 512; ksz <<= 1)
    for (int jsz = ksz>>1; jsz > 0; jsz >>= 1) {
      if (tid < 512) {
        int ixj = tid ^ jsz;
        if (ixj > tid) {
          bool asc = ((tid & ksz) == 0);
          unsigned long long a = sel2[tid], b = sel2[ixj];
          if ((a > b) == asc) { sel2[tid]=b; sel2[ixj]=a; }
        }
      }
      __syncthreads();
    }
  if (tid < NK) {
    int idx = (int)(sel2[tid] & 0x7FFFull);
    d_keep[tid] = idx; d_sk[tid] = d_si[idx];
    d_stk[tid] = ss[idx]; d_enk[tid] = se[idx];
  }
}

__global__ void k_gather() {
  int i = blockIdx.x, src = d_keep[i];
  float4* d = (float4*)(d_gk + (size_t)i*KG);
  const float4* s = (const float4*)(d_g + (size_t)src*KG);
  for (int k = threadIdx.x; k < KG/4; k += blockDim.x) d[k] = s[k];
}

__global__ void k_dist(const float* __restrict__ pw1, const float* __restrict__ demb) {
  int idx = threadIdx.x + blockIdx.x*blockDim.x;
  if (idx < 9*150) {
    int b = idx/150, n = idx - b*150;
    float acc = 0.f;
#pragma unroll
    for (int f = 0; f < 20; f++) acc += pw1[(size_t)n*3680 + 3660 + f] * demb[b*20+f];
    d_Dd[b*150+n] = acc;
  }
}

__global__ void k_pprod() {
  int r = blockIdx.x, i = r / NA, a = r - i*NA;
  int j = i - 1 - a; int jc = j < 0 ? 0 : (j > NK-1 ? NK-1 : j);
  const float4* gi = (const float4*)(d_gk + (size_t)i*KG);
  const float4* gj = (const float4*)(d_gk + (size_t)jc*KG);
  float4* o = (float4*)(d_prod + (size_t)r*KG);
  for (int k = threadIdx.x; k < KG/4; k += blockDim.x) {
    float4 x = gi[k], y = gj[k];
    o[k] = make_float4(x.x*y.x, x.y*y.y, x.z*y.z, x.w*y.w);
  }
}

__global__ void k_pairfix(const float* __restrict__ pb1) {
  int r = blockIdx.x, i = r / NA, a = r - i*NA;
  int j = i - 1 - a; int jc = j < 0 ? 0 : (j > NK-1 ? NK-1 : j);
  int b = binfn(d_enk[i] - d_stk[jc]);
  int n = threadIdx.x;
  if (n < 150) {
    float v = d_h1[(size_t)r*LDH + n] + d_Ai[i*150+n] + d_Bj[jc*150+n] + d_Dd[b*150+n] + pb1[n];
    d_h1[(size_t)r*LDH + n] = v > 0.f ? v : 0.f;
  }
}

__global__ void k_final(float* __restrict__ out) {
  int i = blockIdx.x, a = threadIdx.x;
  if (a < 128) {
    int j = i - 1 - a; int jc = j < 0 ? 0 : (j > NK-1 ? NK-1 : j);
    float v = (j >= 0) ? d_sk[i] + d_sk[jc] + d_ps[i*NA + a] : -1e9f;
    out[i*129 + a] = v;
  } else if (a == 128) out[i*129 + 128] = 0.f;
}

static inline dim3 gg(int M, int N) { return dim3((M+63)/64, (N+159)/160); }

extern "C" void kernel_launch(void* const* d_in, const int* in_sizes, int n_in,
                              void* d_out, int out_size) {
  const int* tok = (const int*)d_in[0];
  const int* ss  = (const int*)d_in[1];
  const int* se  = (const int*)d_in[2];
  const float* emb   = (const float*)d_in[3];
  const float* wih_f = (const float*)d_in[4];
  const float* whh_f = (const float*)d_in[5];
  const float* b_f   = (const float*)d_in[6];
  const float* wih_b = (const float*)d_in[7];
  const float* whh_b = (const float*)d_in[8];
  const float* b_b   = (const float*)d_in[9];
  const float* aw1 = (const float*)d_in[10]; const float* ab1 = (const float*)d_in[11];
  const float* aw2 = (const float*)d_in[12]; const float* ab2 = (const float*)d_in[13];
  const float* aw3 = (const float*)d_in[14]; const float* ab3 = (const float*)d_in[15];
  const float* wemb = (const float*)d_in[16];
  const float* mw1 = (const float*)d_in[17]; const float* mb1 = (const float*)d_in[18];
  const float* mw2 = (const float*)d_in[19]; const float* mb2 = (const float*)d_in[20];
  const float* mw3 = (const float*)d_in[21]; const float* mb3 = (const float*)d_in[22];
  const float* demb = (const float*)d_in[23];
  const float* pw1 = (const float*)d_in[24]; const float* pb1 = (const float*)d_in[25];
  const float* pw2 = (const float*)d_in[26]; const float* pb2 = (const float*)d_in[27];
  const float* pw3 = (const float*)d_in[28]; const float* pb3 = (const float*)d_in[29];
  float* out = (float*)d_out;

  float* Xf; float* states; float* h1; float* h2; float* g; float* prod; float* gk;
  float* Ai; float* Bj; float* attns; float* si; float* ps;
  cudaGetSymbolAddress((void**)&Xf, d_Xbuf);
  cudaGetSymbolAddress((void**)&states, d_states);
  cudaGetSymbolAddress((void**)&h1, d_h1);
  cudaGetSymbolAddress((void**)&h2, d_h2);
  cudaGetSymbolAddress((void**)&g, d_g);
  cudaGetSymbolAddress((void**)&prod, d_prod);
  cudaGetSymbolAddress((void**)&gk, d_gk);
  cudaGetSymbolAddress((void**)&Ai, d_Ai);
  cudaGetSymbolAddress((void**)&Bj, d_Bj);
  cudaGetSymbolAddress((void**)&attns, d_attns);
  cudaGetSymbolAddress((void**)&si, d_si);
  cudaGetSymbolAddress((void**)&ps, d_ps);
  float* embeds; cudaGetSymbolAddress((void**)&embeds, d_embeds);

  k_embed<<<T_, 128>>>(tok, emb);
  k_gemm<<<gg(T_,800), 256>>>(embeds, wih_f, b_f, Xf,            T_, 800, 400, 400, 400, 800, 0);
  k_gemm<<<gg(T_,800), 256>>>(embeds, wih_b, b_b, Xf + T_*800,   T_, 800, 400, 400, 400, 800, 0);

  cudaLaunchConfig_t cfg = {};
  cfg.gridDim = dim3(8,1,1); cfg.blockDim = dim3(400,1,1);
  cudaLaunchAttribute attr[1];
  attr[0].id = cudaLaunchAttributeClusterDimension;
  attr[0].val.clusterDim.x = 4; attr[0].val.clusterDim.y = 1; attr[0].val.clusterDim.z = 1;
  cfg.attrs = attr; cfg.numAttrs = 1; cfg.stream = 0;
  cudaLaunchKernelEx(&cfg, k_lstm, whh_f, whh_b);

  // attention MLP over tokens
  k_gemm<<<gg(T_,150), 256>>>(states, aw1, ab1, h1, T_, 150, 400, 400, 400, LDH, 1);
  k_gemm<<<gg(T_,150), 256>>>(h1, aw2, ab2, h2,     T_, 150, 150, LDH, 150, LDH, 1);
  k_dot3<<<(T_+7)/8, 256>>>(h2, aw3, ab3, attns, T_, LDH);

  k_spang<<<NS, 128>>>(ss, se, wemb);

  // mention MLP
  k_gemm<<<gg(NS,150), 256>>>(g, mw1, mb1, h1, NS, 150, KG, KG, KG, LDH, 1);
  k_gemm<<<gg(NS,150), 256>>>(h1, mw2, mb2, h2, NS, 150, 150, LDH, 150, LDH, 1);
  k_dot3<<<(NS+7)/8, 256>>>(h2, mw3, mb3, si, NS, LDH);

  k_topk<<<1, 1024>>>(ss, se);
  k_gather<<<NK, 128>>>();

  // pair MLP (decomposed)
  k_gemm<<<gg(NK,150), 256>>>(gk, pw1,        0, Ai, NK, 150, KG, KG, 3680, 150, 0);
  k_gemm<<<gg(NK,150), 256>>>(gk, pw1 + 1220, 0, Bj, NK, 150, KG, KG, 3680, 150, 0);
  k_dist<<<6, 256>>>(pw1, demb);
  k_pprod<<<NP, 256>>>();
  k_gemm<<<gg(NP,150), 256>>>(prod, pw1 + 2440, 0, h1, NP, 150, KG, KG, 3680, LDH, 0);
  k_pairfix<<<NP, 160>>>(pb1);
  k_gemm<<<gg(NP,150), 256>>>(h1, pw2, pb2, h2, NP, 150, 150, LDH, 150, LDH, 1);
  k_dot3<<<(NP+7)/8, 256>>>(h2, pw3, pb3, ps, NP, LDH);

  k_final<<<NK, 160>>>(out);
}

// round 3
// speedup vs baseline: 1.5796x; 1.5796x over previous
#include <cuda_runtime.h>
#include <cuda_bf16.h>
#include <math.h>
#include <stdint.h>

#define T_  2048
#define E_  400
#define NS  20480
#define NK  384
#define NA  128
#define NP  (NK*NA)
#define KG  1220
#define LDH 152

__device__ float d_embeds[T_ * E_];
__device__ float d_Xbuf[2 * T_ * 800];
__device__ float d_states[T_ * 400];
__device__ float d_attns[T_];
__device__ float d_g[(size_t)NS * KG];
__device__ float d_h1[(size_t)NP * LDH];
__device__ float d_h2[(size_t)NP * LDH];
__device__ float d_si[NS];
__device__ int   d_keep[NK];
__device__ float d_sk[NK];
__device__ int   d_stk[NK];
__device__ int   d_enk[NK];
__device__ float d_gk[NK * KG];
__device__ float d_Ai[NK * 150];
__device__ float d_Bj[NK * 150];
__device__ float d_Dd[9 * 150];
__device__ float d_ps[NP];

__device__ __forceinline__ int binfn(int x) {
  return (x>=1)+(x>=2)+(x>=3)+(x>=4)+(x>=8)+(x>=16)+(x>=32)+(x>=64);
}
__device__ __forceinline__ uint32_t s2u(const void* p) {
  uint32_t a; asm("{ .reg .u64 t; cvta.to.shared.u64 t, %1; cvt.u32.u64 %0, t; }" : "=r"(a) : "l"(p));
  return a;
}
__device__ __forceinline__ void csync() {
  asm volatile("barrier.cluster.arrive.aligned;" ::: "memory");
  asm volatile("barrier.cluster.wait.aligned;" ::: "memory");
}
__device__ __forceinline__ void fma2(unsigned long long& d, unsigned long long a, unsigned long long b) {
  asm("fma.rn.f32x2 %0, %1, %2, %0;" : "+l"(d) : "l"(a), "l"(b));
}
__device__ __forceinline__ float2 unpk(unsigned long long v) {
  float2 r; asm("mov.b64 {%0,%1}, %2;" : "=f"(r.x), "=f"(r.y) : "l"(v)); return r;
}
__device__ __forceinline__ void mbar_wait(uint32_t mbar, uint32_t ph) {
  uint32_t done = 0;
  while (!done) {
    asm volatile("{ .reg .pred p; mbarrier.try_wait.parity.acquire.cluster.shared::cta.b64 p, [%1], %2, 0x989680; selp.b32 %0, 1, 0, p; }"
                 : "=r"(done) : "r"(mbar), "r"(ph) : "memory");
  }
}

// ---------------- embedding gather ----------------
__global__ void k_embed(const int* __restrict__ tok, const float* __restrict__ emb) {
  int t = blockIdx.x; int row = tok[t];
  const float4* s = (const float4*)(emb + (size_t)row * E_);
  float4* d = (float4*)(d_embeds + (size_t)t * E_);
  for (int i = threadIdx.x; i < E_/4; i += blockDim.x) d[i] = s[i];
}

// ---------------- SGEMM 128x160 tile, f32x2: C = act(A@W^T + bias) ----------------
// requires M % 128 == 0. dyn smem: As 32x132 f32 (16896B) + Ws 32x164 f32x2 (41984B)
#define GEMM_SMEM (16896 + 41984)
__global__ void __launch_bounds__(256,2) k_gemm(const float* __restrict__ A, const float* __restrict__ W,
                       const float* __restrict__ bias, float* __restrict__ C,
                       int M, int N, int K, int lda, int wstride, int ldc, int relu)
{
  extern __shared__ char smx[];
  float (*As)[132] = (float(*)[132])smx;
  float2 (*Ws)[164] = (float2(*)[164])(smx + 16896);
  int tid = threadIdx.x, tx = tid & 15, ty = tid >> 4;
  int row0 = blockIdx.x * 128, col0 = blockIdx.y * 160;
  unsigned long long acc[4][10];
#pragma unroll
  for (int p=0;p<4;p++)
#pragma unroll
    for (int j=0;j<10;j++) acc[p][j] = 0ull;

  for (int k0 = 0; k0 < K; k0 += 32) {
    int ks = K - k0; if (ks > 32) ks = 32;
#pragma unroll
    for (int it = 0; it < 4; it++) {
      int idx = tid + it*256, m = idx>>3, q = idx&7;
      float4 v = make_float4(0.f,0.f,0.f,0.f);
      if (q*4 < ks) v = *(const float4*)(A + (size_t)(row0+m)*lda + k0 + q*4);
      As[q*4+0][m]=v.x; As[q*4+1][m]=v.y; As[q*4+2][m]=v.z; As[q*4+3][m]=v.w;
    }
    for (int idx = tid; idx < 160*32; idx += 256) {
      int n = idx>>5, k = idx&31, ng = col0 + n;
      float w = (ng < N && k < ks) ? W[(size_t)ng*wstride + k0 + k] : 0.f;
      Ws[k][n] = make_float2(w, w);
    }
    __syncthreads();
#pragma unroll
    for (int k = 0; k < 32; k++) {
      const ulonglong2* ap = (const ulonglong2*)&As[k][ty*8];
      ulonglong2 A01 = ap[0], A23 = ap[1];
#pragma unroll
      for (int j = 0; j < 10; j++) {
        unsigned long long wv = *(const unsigned long long*)&Ws[k][j*16 + tx];
        fma2(acc[0][j], A01.x, wv);
        fma2(acc[1][j], A01.y, wv);
        fma2(acc[2][j], A23.x, wv);
        fma2(acc[3][j], A23.y, wv);
      }
    }
    __syncthreads();
  }
#pragma unroll
  for (int p=0;p<4;p++) {
    int r0 = row0 + ty*8 + p*2;
#pragma unroll
    for (int j=0;j<10;j++) {
      int col = col0 + j*16 + tx; if (col >= N) continue;
      float2 v = unpk(acc[p][j]);
      float b = bias ? bias[col] : 0.f;
      float v0 = v.x + b, v1 = v.y + b;
      if (relu) { v0 = v0>0.f?v0:0.f; v1 = v1>0.f?v1:0.f; }
      C[(size_t)r0*ldc + col] = v0;
      C[(size_t)(r0+1)*ldc + col] = v1;
    }
  }
}

// ---------------- pair h1: fused gi*gj product + GEMM + Ai/Bj/Dd/bias/relu ----------------
__global__ void __launch_bounds__(256,2) k_pgemm(const float* __restrict__ pb1)
{
  extern __shared__ char smx[];
  float (*As)[132] = (float(*)[132])smx;
  float2 (*Ws)[164] = (float2(*)[164])(smx + 16896);
  __shared__ int jcs[128];
  __shared__ int bins[128];
  const float* W = 0; // set below (pw1+2440 passed via d_ptr trick avoided: pass as param)
  int i = blockIdx.x;
  int tid = threadIdx.x, tx = tid & 15, ty = tid >> 4;
  if (tid < 128) {
    int j = i - 1 - tid;
    int jc = j < 0 ? 0 : (j > NK-1 ? NK-1 : j);
    jcs[tid] = jc;
    bins[tid] = binfn(d_enk[i] - d_stk[jc]);
  }
  __syncthreads();
  (void)W;
  unsigned long long acc[4][10];
#pragma unroll
  for (int p=0;p<4;p++)
#pragma unroll
    for (int j=0;j<10;j++) acc[p][j] = 0ull;
  const float* Wp = pb1 + 150; // placeholder, replaced by real param below
  (void)Wp;
  // real weight pointer passed via constant global below
  extern __device__ float* d_pw1c;
  const float* pw1 = d_pw1c;
  const float* Wk = pw1 + 2440;

  for (int k0 = 0; k0 < KG; k0 += 32) {
    int ks = KG - k0; if (ks > 32) ks = 32;
#pragma unroll
    for (int it = 0; it < 4; it++) {
      int idx = tid + it*256, m = idx>>3, q = idx&7;
      float4 v = make_float4(0.f,0.f,0.f,0.f);
      if (q*4 < ks) {
        float4 a = *(const float4*)(d_gk + (size_t)i*KG + k0 + q*4);
        float4 b = *(const float4*)(d_gk + (size_t)jcs[m]*KG + k0 + q*4);
        v = make_float4(a.x*b.x, a.y*b.y, a.z*b.z, a.w*b.w);
      }
      As[q*4+0][m]=v.x; As[q*4+1][m]=v.y; As[q*4+2][m]=v.z; As[q*4+3][m]=v.w;
    }
    for (int idx = tid; idx < 160*32; idx += 256) {
      int n = idx>>5, k = idx&31;
      float w = (n < 150 && k < ks) ? Wk[(size_t)n*3680 + k0 + k] : 0.f;
      Ws[k][n] = make_float2(w, w);
    }
    __syncthreads();
#pragma unroll
    for (int k = 0; k < 32; k++) {
      const ulonglong2* ap = (const ulonglong2*)&As[k][ty*8];
      ulonglong2 A01 = ap[0], A23 = ap[1];
#pragma unroll
      for (int j = 0; j < 10; j++) {
        unsigned long long wv = *(const unsigned long long*)&Ws[k][j*16 + tx];
        fma2(acc[0][j], A01.x, wv);
        fma2(acc[1][j], A01.y, wv);
        fma2(acc[2][j], A23.x, wv);
        fma2(acc[3][j], A23.y, wv);
      }
    }
    __syncthreads();
  }
#pragma unroll
  for (int p=0;p<4;p++) {
    int m0 = ty*8 + p*2;
#pragma unroll
    for (int j=0;j<10;j++) {
      int col = j*16 + tx; if (col >= 150) continue;
      float2 v = unpk(acc[p][j]);
      float ai = d_Ai[i*150 + col];
      float b  = pb1[col];
      float v0 = v.x + ai + d_Bj[jcs[m0]*150+col]   + d_Dd[bins[m0]*150+col]   + b;
      float v1 = v.y + ai + d_Bj[jcs[m0+1]*150+col] + d_Dd[bins[m0+1]*150+col] + b;
      v0 = v0>0.f?v0:0.f; v1 = v1>0.f?v1:0.f;
      d_h1[(size_t)(i*128+m0)*LDH + col] = v0;
      d_h1[(size_t)(i*128+m0+1)*LDH + col] = v1;
    }
  }
}
__device__ float* d_pw1c;
__global__ void k_setpw1(const float* p) { if (threadIdx.x==0) d_pw1c = (float*)p; }

// ---------------- LSTM: cluster of 8 CTAs/direction, st.async + mbarrier ping-pong ----------------
__global__ void __launch_bounds__(400,1) k_lstm(const float* __restrict__ whhf,
                                                const float* __restrict__ whhb)
{
  int rank = blockIdx.x & 7, dir = blockIdx.x >> 3;
  const float* whh = dir ? whhb : whhf;
  const float* X = d_Xbuf + (size_t)dir * T_ * 800;
  int tid = threadIdx.x, gid = tid >> 2, quarter = tid & 3;
  int q = gid / 25, tloc = gid - q*25;
  int grow = q*200 + rank*25 + tloc;
  unsigned long long w2[25];
  {
    const unsigned long long* wp = (const unsigned long long*)(whh + (size_t)grow*200 + quarter*50);
#pragma unroll
    for (int j = 0; j < 25; j++) w2[j] = wp[j];
  }
  __shared__ __align__(16) float hbuf[2][208];
  __shared__ float gbuf[104];
  __shared__ __align__(8) unsigned long long mb[2];
  if (tid < 200) { hbuf[0][tid] = 0.f; }
  if (tid == 0) {
    asm volatile("mbarrier.init.shared.b64 [%0], 1;" :: "r"(s2u(&mb[0])) : "memory");
    asm volatile("mbarrier.init.shared.b64 [%0], 1;" :: "r"(s2u(&mb[1])) : "memory");
  }
  float c = 0.f;
  __syncthreads();
  csync();
  uint32_t mba0 = s2u(&mb[0]), mba1 = s2u(&mb[1]);
  uint32_t hb0 = s2u(&hbuf[0][0]), hb1 = s2u(&hbuf[1][0]);
  uint32_t ph0 = 0, ph1 = 0;
  for (int s = 0; s < T_; s++) {
    int tt = dir ? (T_-1-s) : s;
    int qq = s & 1;
    float x = 0.f;
    if (quarter == 0) x = X[(size_t)tt*800 + grow];
    if (s > 0) {
      uint32_t mba = qq ? mba1 : mba0;
      if (tid == 0)
        asm volatile("mbarrier.arrive.expect_tx.shared.b64 _, [%0], %1;" :: "r"(mba), "r"(800u) : "memory");
      mbar_wait(mba, qq ? ph1 : ph0);
      if (qq) ph1 ^= 1; else ph0 ^= 1;
    }
    const float* hb = hbuf[qq];
    unsigned long long acc2 = 0ull;
    const unsigned long long* hp = (const unsigned long long*)(hb + quarter*50);
#pragma unroll
    for (int jj = 0; jj < 25; jj++) fma2(acc2, w2[jj], hp[jj]);
    float2 av = unpk(acc2);
    float r = av.x + av.y;
    unsigned am = __activemask();
    r += __shfl_xor_sync(am, r, 1);
    r += __shfl_xor_sync(am, r, 2);
    if (quarter == 0) gbuf[gid] = r + x;
    __syncthreads();
    if (tid < 25) {
      float ig = 1.f/(1.f+expf(-gbuf[tid]));
      float fg = 1.f/(1.f+expf(-gbuf[25+tid]));
      float gg = tanhf(gbuf[50+tid]);
      float og = 1.f/(1.f+expf(-gbuf[75+tid]));
      c = fg*c + ig*gg;
      float h = og * tanhf(c);
      int hg = rank*25 + tid;
      d_states[(size_t)tt*400 + dir*200 + hg] = h;
      if (s < T_-1) {
        uint32_t la = (qq ? hb0 : hb1) + hg*4u;
        uint32_t lm = qq ? mba0 : mba1;
        unsigned hv = __float_as_uint(h);
#pragma unroll
        for (int pe = 0; pe < 8; pe++) {
          asm volatile("{ .reg .b32 ra, rm; mapa.shared::cluster.u32 ra, %0, %2; mapa.shared::cluster.u32 rm, %1, %2; "
                       "st.async.shared::cluster.mbarrier::complete_tx::bytes.b32 [ra], %3, [rm]; }"
                       :: "r"(la), "r"(lm), "r"(pe), "r"(hv) : "memory");
        }
      }
    }
  }
  csync();
}

// ---------------- per-row dot: out[r] = h2[r]·w3 + b3 ----------------
__global__ void k_dot3(const float* __restrict__ h2, const float* __restrict__ w3,
                       const float* __restrict__ b3, float* __restrict__ out, int M, int lda)
{
  int row = blockIdx.x*8 + (threadIdx.x>>5), lane = threadIdx.x & 31;
  if (row >= M) return;
  const float* hp = h2 + (size_t)row*lda;
  float pSum = 0.f;
  for (int k = lane; k < 150; k += 32) pSum += hp[k]*w3[k];
#pragma unroll
  for (int o = 16; o > 0; o >>= 1) pSum += __shfl_down_sync(0xffffffffu, pSum, o);
  if (lane == 0) out[row] = pSum + b3[0];
}

// ---------------- span feature build ----------------
__global__ void k_spang(const int* __restrict__ ss, const int* __restrict__ se,
                        const float* __restrict__ wemb)
{
  int sp = blockIdx.x, st = ss[sp], en = se[sp], width = en - st + 1;
  __shared__ float aw[10];
  int tid = threadIdx.x;
  if (tid < 10) {
    int ix = st + tid; if (ix > T_-1) ix = T_-1;
    aw[tid] = (tid < width) ? d_attns[ix] : -1e9f;
  }
  __syncthreads();
  float mx = aw[0];
#pragma unroll
  for (int w2 = 1; w2 < 10; w2++) mx = fmaxf(mx, aw[w2]);
  float wt[10], ssum = 0.f;
#pragma unroll
  for (int w2 = 0; w2 < 10; w2++) { float e = expf(aw[w2]-mx); wt[w2]=e; ssum+=e; }
  float inv = 1.f/ssum;
  float* grow = d_g + (size_t)sp*KG;
  for (int e = tid; e < 400; e += blockDim.x) {
    grow[e]     = d_states[(size_t)st*400 + e];
    grow[400+e] = d_states[(size_t)en*400 + e];
    float acc = 0.f;
#pragma unroll
    for (int w2 = 0; w2 < 10; w2++) {
      int ix = st + w2; if (ix > T_-1) ix = T_-1;
      acc += wt[w2] * d_embeds[(size_t)ix*E_ + e];
    }
    grow[800+e] = acc * inv;
  }
  if (tid < 20) grow[1200+tid] = wemb[binfn(width)*20 + tid];
}

// ---------------- exact top-k + positional stable sort ----------------
__global__ void __launch_bounds__(1024) k_topk(const int* __restrict__ ss, const int* __restrict__ se)
{
  int tid = threadIdx.x;
  unsigned long long key[20];
#pragma unroll
  for (int i = 0; i < 20; i++) {
    int idx = i*1024 + tid;
    unsigned u = __float_as_uint(d_si[idx]);
    u = (u & 0x80000000u) ? ~u : (u | 0x80000000u);
    key[i] = ((unsigned long long)u << 32) | (unsigned long long)(0xFFFFFFFFu - (unsigned)idx);
  }
  __shared__ int cnt, selc;
  __shared__ unsigned long long sel[512], sel2[512];
  unsigned long long lo = 0ull, hi = ~0ull;
  while (lo < hi) {
    unsigned long long mid = lo + ((hi-lo)>>1) + 1ull;
    if (tid == 0) cnt = 0;
    __syncthreads();
    int c = 0;
#pragma unroll
    for (int i = 0; i < 20; i++) c += (key[i] >= mid);
#pragma unroll
    for (int o = 16; o > 0; o >>= 1) c += __shfl_down_sync(0xffffffffu, c, o);
    if ((tid&31)==0) atomicAdd(&cnt, c);
    __syncthreads();
    int total = cnt;
    __syncthreads();
    if (total >= NK) lo = mid; else hi = mid - 1ull;
  }
  if (tid == 0) selc = 0;
  __syncthreads();
#pragma unroll
  for (int i = 0; i < 20; i++)
    if (key[i] >= lo) { int pp = atomicAdd(&selc, 1); if (pp < 512) sel[pp] = key[i]; }
  __syncthreads();
  if (tid < 512 && tid >= selc) sel[tid] = 0ull;
  __syncthreads();
  for (int ksz = 2; ksz <= 512; ksz <<= 1)
    for (int jsz = ksz>>1; jsz > 0; jsz >>= 1) {
      if (tid < 512) {
        int ixj = tid ^ jsz;
        if (ixj > tid) {
          bool asc = ((tid & ksz) == 0);
          unsigned long long a = sel[tid], b = sel[ixj];
          if ((a > b) == asc) { sel[tid]=b; sel[ixj]=a; }
        }
      }
      __syncthreads();
    }
  if (tid < 512) {
    if (tid < NK) {
      unsigned long long kk = sel[511 - tid];
      unsigned idx = 0xFFFFFFFFu - (unsigned)(kk & 0xFFFFFFFFull);
      unsigned st = (unsigned)ss[idx], en = (unsigned)se[idx];
      unsigned long long pos = (unsigned long long)(st*2049u + en);
      sel2[tid] = (pos << 24) | ((unsigned long long)tid << 15) | (unsigned long long)idx;
    } else sel2[tid] = ~0ull;
  }
  __syncthreads();
  for (int ksz = 2; ksz <= 512; ksz <<= 1)
    for (int jsz = ksz>>1; jsz > 0; jsz >>= 1) {
      if (tid < 512) {
        int ixj = tid ^ jsz;
        if (ixj > tid) {
          bool asc = ((tid & ksz) == 0);
          unsigned long long a = sel2[tid], b = sel2[ixj];
          if ((a > b) == asc) { sel2[tid]=b; sel2[ixj]=a; }
        }
      }
      __syncthreads();
    }
  if (tid < NK) {
    int idx = (int)(sel2[tid] & 0x7FFFull);
    d_keep[tid] = idx; d_sk[tid] = d_si[idx];
    d_stk[tid] = ss[idx]; d_enk[tid] = se[idx];
  }
}

__global__ void k_gather() {
  int i = blockIdx.x, src = d_keep[i];
  float4* d = (float4*)(d_gk + (size_t)i*KG);
  const float4* s = (const float4*)(d_g + (size_t)src*KG);
  for (int k = threadIdx.x; k < KG/4; k += blockDim.x) d[k] = s[k];
}

__global__ void k_zeroAB() {
  int idx = threadIdx.x + blockIdx.x*blockDim.x;
  if (idx < NK*150) { d_Ai[idx] = 0.f; d_Bj[idx] = 0.f; }
}

// Ai/Bj split-K GEMM: grid (NK/32, 10): y<5 -> Ai, else Bj; ksplit = y%5 (chunk 244)
__global__ void __launch_bounds__(160) k_abgemm(const float* __restrict__ pw1) {
  __shared__ float As2[244][32];
  int rb = blockIdx.x, yz = blockIdx.y;
  int mat = yz / 5, ks5 = yz % 5;
  const float* W = pw1 + mat*1220;
  float* O = mat ? d_Bj : d_Ai;
  int k0 = ks5*244;
  int tid = threadIdx.x;
  for (int idx = tid; idx < 244*32; idx += 160) {
    int k = idx >> 5, r = idx & 31;
    As2[k][r] = d_gk[(size_t)(rb*32+r)*KG + k0 + k];
  }
  __syncthreads();
  int col = tid;
  float acc[32];
#pragma unroll
  for (int r = 0; r < 32; r++) acc[r] = 0.f;
  if (col < 150) {
    const float* wr = W + (size_t)col*3680 + k0;
    for (int k = 0; k < 244; k++) {
      float w = wr[k];
      const float4* ar = (const float4*)As2[k];
#pragma unroll
      for (int r4 = 0; r4 < 8; r4++) {
        float4 a = ar[r4];
        acc[r4*4+0] += a.x*w; acc[r4*4+1] += a.y*w;
        acc[r4*4+2] += a.z*w; acc[r4*4+3] += a.w*w;
      }
    }
#pragma unroll
    for (int r = 0; r < 32; r++) atomicAdd(&O[(rb*32+r)*150 + col], acc[r]);
  }
}

__global__ void k_dist(const float* __restrict__ pw1, const float* __restrict__ demb) {
  int idx = threadIdx.x + blockIdx.x*blockDim.x;
  if (idx < 9*150) {
    int b = idx/150, n = idx - b*150;
    float acc = 0.f;
#pragma unroll
    for (int f = 0; f < 20; f++) acc += pw1[(size_t)n*3680 + 3660 + f] * demb[b*20+f];
    d_Dd[b*150+n] = acc;
  }
}

__global__ void k_final(float* __restrict__ out) {
  int i = blockIdx.x, a = threadIdx.x;
  if (a < 128) {
    int j = i - 1 - a; int jc = j < 0 ? 0 : (j > NK-1 ? NK-1 : j);
    float v = (j >= 0) ? d_sk[i] + d_sk[jc] + d_ps[i*NA + a] : -1e9f;
    out[i*129 + a] = v;
  } else if (a == 128) out[i*129 + 128] = 0.f;
}

static inline dim3 gg(int M, int N) { return dim3((M+127)/128, (N+159)/160); }

extern "C" void kernel_launch(void* const* d_in, const int* in_sizes, int n_in,
                              void* d_out, int out_size) {
  const int* tok = (const int*)d_in[0];
  const int* ss  = (const int*)d_in[1];
  const int* se  = (const int*)d_in[2];
  const float* emb   = (const float*)d_in[3];
  const float* wih_f = (const float*)d_in[4];
  const float* whh_f = (const float*)d_in[5];
  const float* b_f   = (const float*)d_in[6];
  const float* wih_b = (const float*)d_in[7];
  const float* whh_b = (const float*)d_in[8];
  const float* b_b   = (const float*)d_in[9];
  const float* aw1 = (const float*)d_in[10]; const float* ab1 = (const float*)d_in[11];
  const float* aw2 = (const float*)d_in[12]; const float* ab2 = (const float*)d_in[13];
  const float* aw3 = (const float*)d_in[14]; const float* ab3 = (const float*)d_in[15];
  const float* wemb = (const float*)d_in[16];
  const float* mw1 = (const float*)d_in[17]; const float* mb1 = (const float*)d_in[18];
  const float* mw2 = (const float*)d_in[19]; const float* mb2 = (const float*)d_in[20];
  const float* mw3 = (const float*)d_in[21]; const float* mb3 = (const float*)d_in[22];
  const float* demb = (const float*)d_in[23];
  const float* pw1 = (const float*)d_in[24]; const float* pb1 = (const float*)d_in[25];
  const float* pw2 = (const float*)d_in[26]; const float* pb2 = (const float*)d_in[27];
  const float* pw3 = (const float*)d_in[28]; const float* pb3 = (const float*)d_in[29];
  float* out = (float*)d_out;

  static int attr_done = 0;
  if (!attr_done) {
    cudaFuncSetAttribute(k_gemm, cudaFuncAttributeMaxDynamicSharedMemorySize, GEMM_SMEM);
    cudaFuncSetAttribute(k_pgemm, cudaFuncAttributeMaxDynamicSharedMemorySize, GEMM_SMEM);
    attr_done = 1;
  }

  float* Xf; float* states; float* h1; float* h2; float* g; float* attns; float* si; float* ps;
  float* embeds;
  cudaGetSymbolAddress((void**)&Xf, d_Xbuf);
  cudaGetSymbolAddress((void**)&states, d_states);
  cudaGetSymbolAddress((void**)&h1, d_h1);
  cudaGetSymbolAddress((void**)&h2, d_h2);
  cudaGetSymbolAddress((void**)&g, d_g);
  cudaGetSymbolAddress((void**)&attns, d_attns);
  cudaGetSymbolAddress((void**)&si, d_si);
  cudaGetSymbolAddress((void**)&ps, d_ps);
  cudaGetSymbolAddress((void**)&embeds, d_embeds);

  k_setpw1<<<1,32>>>(pw1);
  k_embed<<<T_, 128>>>(tok, emb);
  k_gemm<<<gg(T_,800), 256, GEMM_SMEM>>>(embeds, wih_f, b_f, Xf,          T_, 800, 400, 400, 400, 800, 0);
  k_gemm<<<gg(T_,800), 256, GEMM_SMEM>>>(embeds, wih_b, b_b, Xf + T_*800, T_, 800, 400, 400, 400, 800, 0);

  {
    cudaLaunchConfig_t cfg = {};
    cfg.gridDim = dim3(16,1,1); cfg.blockDim = dim3(400,1,1);
    cudaLaunchAttribute attr[1];
    attr[0].id = cudaLaunchAttributeClusterDimension;
    attr[0].val.clusterDim.x = 8; attr[0].val.clusterDim.y = 1; attr[0].val.clusterDim.z = 1;
    cfg.attrs = attr; cfg.numAttrs = 1; cfg.stream = 0;
    cudaLaunchKernelEx(&cfg, k_lstm, whh_f, whh_b);
  }

  // attention MLP over tokens
  k_gemm<<<gg(T_,150), 256, GEMM_SMEM>>>(states, aw1, ab1, h1, T_, 150, 400, 400, 400, LDH, 1);
  k_gemm<<<gg(T_,150), 256, GEMM_SMEM>>>(h1, aw2, ab2, h2,     T_, 150, 150, LDH, 150, LDH, 1);
  k_dot3<<<(T_+7)/8, 256>>>(h2, aw3, ab3, attns, T_, LDH);

  k_spang<<<NS, 128>>>(ss, se, wemb);

  // mention MLP
  k_gemm<<<gg(NS,150), 256, GEMM_SMEM>>>(g, mw1, mb1, h1, NS, 150, KG, KG, KG, LDH, 1);
  k_gemm<<<gg(NS,150), 256, GEMM_SMEM>>>(h1, mw2, mb2, h2, NS, 150, 150, LDH, 150, LDH, 1);
  k_dot3<<<(NS+7)/8, 256>>>(h2, mw3, mb3, si, NS, LDH);

  k_topk<<<1, 1024>>>(ss, se);
  k_gather<<<NK, 128>>>();

  // pair MLP (decomposed + fused)
  k_zeroAB<<<(NK*150+255)/256, 256>>>();
  k_abgemm<<<dim3(NK/32, 10), 160>>>(pw1);
  k_dist<<<6, 256>>>(pw1, demb);
  k_pgemm<<<NK, 256, GEMM_SMEM>>>(pb1);
  k_gemm<<<gg(NP,150), 256, GEMM_SMEM>>>(h1, pw2, pb2, h2, NP, 150, 150, LDH, 150, LDH, 1);
  k_dot3<<<(NP+7)/8, 256>>>(h2, pw3, pb3, ps, NP, LDH);

  k_final<<<NK, 160>>>(out);
}

// round 4
// speedup vs baseline: 1.5996x; 1.0127x over previous
#include <cuda_runtime.h>
#include <cuda_bf16.h>
#include <math.h>
#include <stdint.h>

#define T_  2048
#define E_  400
#define NS  20480
#define NK  384
#define NA  128
#define NP  (NK*NA)
#define KG  1220
#define LDH 152
#define KB  16

__device__ float d_embeds[T_ * E_];
__device__ float d_Xbuf[2 * T_ * 800];
__device__ float d_states[T_ * 400];
__device__ float d_attns[T_];
__device__ float d_g[(size_t)NS * KG];
__device__ float d_h1[(size_t)NP * LDH];
__device__ float d_si[NS];
__device__ int   d_keep[NK];
__device__ float d_sk[NK];
__device__ int   d_stk[NK];
__device__ int   d_enk[NK];
__device__ float d_gk[NK * KG];
__device__ float d_Ai[NK * 150];
__device__ float d_Bj[NK * 150];
__device__ float d_Dd[9 * 150];
__device__ float d_ps[NP];
__device__ float* d_pw1c;

__device__ __forceinline__ int binfn(int x) {
  return (x>=1)+(x>=2)+(x>=3)+(x>=4)+(x>=8)+(x>=16)+(x>=32)+(x>=64);
}
__device__ __forceinline__ uint32_t s2u(const void* p) {
  uint32_t a; asm("{ .reg .u64 t; cvta.to.shared.u64 t, %1; cvt.u32.u64 %0, t; }" : "=r"(a) : "l"(p));
  return a;
}
__device__ __forceinline__ void csync() {
  asm volatile("barrier.cluster.arrive.aligned;" ::: "memory");
  asm volatile("barrier.cluster.wait.aligned;" ::: "memory");
}
__device__ __forceinline__ void fma2(unsigned long long& d, unsigned long long a, unsigned long long b) {
  asm("fma.rn.f32x2 %0, %1, %2, %0;" : "+l"(d) : "l"(a), "l"(b));
}
__device__ __forceinline__ float2 unpk(unsigned long long v) {
  float2 r; asm("mov.b64 {%0,%1}, %2;" : "=f"(r.x), "=f"(r.y) : "l"(v)); return r;
}
__device__ __forceinline__ void mbar_wait(uint32_t mbar, uint32_t ph) {
  uint32_t done = 0;
  while (!done) {
    asm volatile("{ .reg .pred p; mbarrier.try_wait.parity.acquire.cluster.shared::cta.b64 p, [%1], %2, 0x989680; selp.b32 %0, 1, 0, p; }"
                 : "=r"(done) : "r"(mbar), "r"(ph) : "memory");
  }
}

// smem layout helpers for pipelined GEMM
#define AS(b,k,m) sA[((b)*KB + (k))*132 + (m)]
#define WS(b,k,n) sW[((b)*KB + (k))*164 + (n)]
#define GEMM_SMEM (2*KB*132*4 + 2*KB*164*8)

// ---------------- embedding gather ----------------
__global__ void k_embed(const int* __restrict__ tok, const float* __restrict__ emb) {
  int t = blockIdx.x; int row = tok[t];
  const float4* s = (const float4*)(emb + (size_t)row * E_);
  float4* d = (float4*)(d_embeds + (size_t)t * E_);
  for (int i = threadIdx.x; i < E_/4; i += blockDim.x) d[i] = s[i];
}

// ---------------- pipelined SGEMM 128xN tile, f32x2, optional fused tail dot ----------------
__global__ void __launch_bounds__(256,2) k_gemm(const float* __restrict__ A, const float* __restrict__ W,
                       const float* __restrict__ bias, float* __restrict__ C,
                       int M, int N, int K, int lda, int wstride, int ldc, int relu,
                       const float* __restrict__ w3, const float* __restrict__ b3,
                       float* __restrict__ outv)
{
  extern __shared__ char smx[];
  float*  sA = (float*)smx;
  float2* sW = (float2*)(smx + 2*KB*132*4);
  int tid = threadIdx.x, tx = tid & 15, ty = tid >> 4;
  int row0 = blockIdx.x * 128, col0 = blockIdx.y * 160;
  unsigned long long acc[4][10];
#pragma unroll
  for (int p=0;p<4;p++)
#pragma unroll
    for (int j=0;j<10;j++) acc[p][j] = 0ull;

  int m_ld = tid >> 2, q_ld = tid & 3;        // A: 2 chunks, idx=tid+256*it
  int nt = (K + KB - 1) / KB;
  float4 rA[2]; float rW[10];

  // prologue: tile 0
  {
    int k0 = 0, ks = K < KB ? K : KB;
#pragma unroll
    for (int it = 0; it < 2; it++) {
      int m = m_ld + it*64;
      rA[it] = (q_ld*4 < ks) ? *(const float4*)(A + (size_t)(row0+m)*lda + k0 + q_ld*4)
                             : make_float4(0.f,0.f,0.f,0.f);
    }
#pragma unroll
    for (int i = 0; i < 10; i++) {
      int idx = tid + i*256, n = idx >> 4, k = idx & 15, ng = col0 + n;
      rW[i] = (ng < N && k < ks) ? W[(size_t)ng*wstride + k0 + k] : 0.f;
    }
#pragma unroll
    for (int it = 0; it < 2; it++) {
      int m = m_ld + it*64;
      AS(0, q_ld*4+0, m) = rA[it].x; AS(0, q_ld*4+1, m) = rA[it].y;
      AS(0, q_ld*4+2, m) = rA[it].z; AS(0, q_ld*4+3, m) = rA[it].w;
    }
#pragma unroll
    for (int i = 0; i < 10; i++) {
      int idx = tid + i*256, n = idx >> 4, k = idx & 15;
      WS(0, k, n) = make_float2(rW[i], rW[i]);
    }
  }
  __syncthreads();

  for (int t = 0; t < nt; t++) {
    int buf = t & 1;
    if (t+1 < nt) {
      int k0 = (t+1)*KB, ks = K - k0; if (ks > KB) ks = KB;
#pragma unroll
      for (int it = 0; it < 2; it++) {
        int m = m_ld + it*64;
        rA[it] = (q_ld*4 < ks) ? *(const float4*)(A + (size_t)(row0+m)*lda + k0 + q_ld*4)
                               : make_float4(0.f,0.f,0.f,0.f);
      }
#pragma unroll
      for (int i = 0; i < 10; i++) {
        int idx = tid + i*256, n = idx >> 4, k = idx & 15, ng = col0 + n;
        rW[i] = (ng < N && k < ks) ? W[(size_t)ng*wstride + k0 + k] : 0.f;
      }
    }
#pragma unroll
    for (int k = 0; k < KB; k++) {
      const ulonglong2* ap = (const ulonglong2*)&AS(buf, k, ty*8);
      ulonglong2 A01 = ap[0], A23 = ap[1];
#pragma unroll
      for (int j = 0; j < 10; j++) {
        unsigned long long wv = *(const unsigned long long*)&WS(buf, k, j*16 + tx);
        fma2(acc[0][j], A01.x, wv);
        fma2(acc[1][j], A01.y, wv);
        fma2(acc[2][j], A23.x, wv);
        fma2(acc[3][j], A23.y, wv);
      }
    }
    if (t+1 < nt) {
      int nb = (t+1) & 1;
#pragma unroll
      for (int it = 0; it < 2; it++) {
        int m = m_ld + it*64;
        AS(nb, q_ld*4+0, m) = rA[it].x; AS(nb, q_ld*4+1, m) = rA[it].y;
        AS(nb, q_ld*4+2, m) = rA[it].z; AS(nb, q_ld*4+3, m) = rA[it].w;
      }
#pragma unroll
      for (int i = 0; i < 10; i++) {
        int idx = tid + i*256, n = idx >> 4, k = idx & 15;
        WS(nb, k, n) = make_float2(rW[i], rW[i]);
      }
    }
    __syncthreads();
  }

  if (outv) {
    // fused: relu(acc+bias) dot w3, reduce over tx, write per-row score
    float b3v = b3[0];
#pragma unroll
    for (int p = 0; p < 4; p++) {
      float p0 = 0.f, p1 = 0.f;
#pragma unroll
      for (int j = 0; j < 10; j++) {
        int col = col0 + j*16 + tx; if (col >= N) continue;
        float2 v = unpk(acc[p][j]);
        float b = bias ? bias[col] : 0.f;
        float v0 = v.x + b, v1 = v.y + b;
        v0 = v0 > 0.f ? v0 : 0.f; v1 = v1 > 0.f ? v1 : 0.f;
        float wc = w3[col];
        p0 += v0 * wc; p1 += v1 * wc;
      }
#pragma unroll
      for (int o = 1; o < 16; o <<= 1) {
        p0 += __shfl_xor_sync(0xffffffffu, p0, o);
        p1 += __shfl_xor_sync(0xffffffffu, p1, o);
      }
      if (tx == 0) {
        int r0 = row0 + ty*8 + p*2;
        outv[r0] = p0 + b3v;
        outv[r0+1] = p1 + b3v;
      }
    }
  } else {
#pragma unroll
    for (int p = 0; p < 4; p++) {
      int r0 = row0 + ty*8 + p*2;
#pragma unroll
      for (int j = 0; j < 10; j++) {
        int col = col0 + j*16 + tx; if (col >= N) continue;
        float2 v = unpk(acc[p][j]);
        float b = bias ? bias[col] : 0.f;
        float v0 = v.x + b, v1 = v.y + b;
        if (relu) { v0 = v0>0.f?v0:0.f; v1 = v1>0.f?v1:0.f; }
        C[(size_t)r0*ldc + col] = v0;
        C[(size_t)(r0+1)*ldc + col] = v1;
      }
    }
  }
}

// ---------------- pair h1: pipelined fused gi*gj GEMM + Ai/Bj/Dd/bias/relu ----------------
__global__ void __launch_bounds__(256,2) k_pgemm(const float* __restrict__ pb1)
{
  extern __shared__ char smx[];
  float*  sA = (float*)smx;
  float2* sW = (float2*)(smx + 2*KB*132*4);
  __shared__ int jcs[128];
  __shared__ int bins[128];
  int i = blockIdx.x;
  int tid = threadIdx.x, tx = tid & 15, ty = tid >> 4;
  if (tid < 128) {
    int j = i - 1 - tid;
    int jc = j < 0 ? 0 : (j > NK-1 ? NK-1 : j);
    jcs[tid] = jc;
    bins[tid] = binfn(d_enk[i] - d_stk[jc]);
  }
  __syncthreads();
  const float* pw1 = d_pw1c;
  const float* Wk = pw1 + 2440;
  const float* gi = d_gk + (size_t)i*KG;

  unsigned long long acc[4][10];
#pragma unroll
  for (int p=0;p<4;p++)
#pragma unroll
    for (int j=0;j<10;j++) acc[p][j] = 0ull;

  int m_ld = tid >> 2, q_ld = tid & 3;
  int nt = (KG + KB - 1) / KB;
  float4 rA[2]; float rW[10];

  {
    int k0 = 0, ks = KB;
#pragma unroll
    for (int it = 0; it < 2; it++) {
      int m = m_ld + it*64;
      if (q_ld*4 < ks) {
        float4 a = *(const float4*)(gi + k0 + q_ld*4);
        float4 b = *(const float4*)(d_gk + (size_t)jcs[m]*KG + k0 + q_ld*4);
        rA[it] = make_float4(a.x*b.x, a.y*b.y, a.z*b.z, a.w*b.w);
      } else rA[it] = make_float4(0.f,0.f,0.f,0.f);
    }
#pragma unroll
    for (int ii = 0; ii < 10; ii++) {
      int idx = tid + ii*256, n = idx >> 4, k = idx & 15;
      rW[ii] = (n < 150 && k < ks) ? Wk[(size_t)n*3680 + k0 + k] : 0.f;
    }
#pragma unroll
    for (int it = 0; it < 2; it++) {
      int m = m_ld + it*64;
      AS(0, q_ld*4+0, m) = rA[it].x; AS(0, q_ld*4+1, m) = rA[it].y;
      AS(0, q_ld*4+2, m) = rA[it].z; AS(0, q_ld*4+3, m) = rA[it].w;
    }
#pragma unroll
    for (int ii = 0; ii < 10; ii++) {
      int idx = tid + ii*256, n = idx >> 4, k = idx & 15;
      WS(0, k, n) = make_float2(rW[ii], rW[ii]);
    }
  }
  __syncthreads();

  for (int t = 0; t < nt; t++) {
    int buf = t & 1;
    if (t+1 < nt) {
      int k0 = (t+1)*KB, ks = KG - k0; if (ks > KB) ks = KB;
#pragma unroll
      for (int it = 0; it < 2; it++) {
        int m = m_ld + it*64;
        if (q_ld*4 < ks) {
          float4 a = *(const float4*)(gi + k0 + q_ld*4);
          float4 b = *(const float4*)(d_gk + (size_t)jcs[m]*KG + k0 + q_ld*4);
          rA[it] = make_float4(a.x*b.x, a.y*b.y, a.z*b.z, a.w*b.w);
        } else rA[it] = make_float4(0.f,0.f,0.f,0.f);
      }
#pragma unroll
      for (int ii = 0; ii < 10; ii++) {
        int idx = tid + ii*256, n = idx >> 4, k = idx & 15;
        rW[ii] = (n < 150 && k < ks) ? Wk[(size_t)n*3680 + k0 + k] : 0.f;
      }
    }
#pragma unroll
    for (int k = 0; k < KB; k++) {
      const ulonglong2* ap = (const ulonglong2*)&AS(buf, k, ty*8);
      ulonglong2 A01 = ap[0], A23 = ap[1];
#pragma unroll
      for (int j = 0; j < 10; j++) {
        unsigned long long wv = *(const unsigned long long*)&WS(buf, k, j*16 + tx);
        fma2(acc[0][j], A01.x, wv);
        fma2(acc[1][j], A01.y, wv);
        fma2(acc[2][j], A23.x, wv);
        fma2(acc[3][j], A23.y, wv);
      }
    }
    if (t+1 < nt) {
      int nb = (t+1) & 1;
#pragma unroll
      for (int it = 0; it < 2; it++) {
        int m = m_ld + it*64;
        AS(nb, q_ld*4+0, m) = rA[it].x; AS(nb, q_ld*4+1, m) = rA[it].y;
        AS(nb, q_ld*4+2, m) = rA[it].z; AS(nb, q_ld*4+3, m) = rA[it].w;
      }
#pragma unroll
      for (int ii = 0; ii < 10; ii++) {
        int idx = tid + ii*256, n = idx >> 4, k = idx & 15;
        WS(nb, k, n) = make_float2(rW[ii], rW[ii]);
      }
    }
    __syncthreads();
  }

#pragma unroll
  for (int p=0;p<4;p++) {
    int m0 = ty*8 + p*2;
#pragma unroll
    for (int j=0;j<10;j++) {
      int col = j*16 + tx; if (col >= 150) continue;
      float2 v = unpk(acc[p][j]);
      float ai = d_Ai[i*150 + col];
      float b  = pb1[col];
      float v0 = v.x + ai + d_Bj[jcs[m0]*150+col]   + d_Dd[bins[m0]*150+col]   + b;
      float v1 = v.y + ai + d_Bj[jcs[m0+1]*150+col] + d_Dd[bins[m0+1]*150+col] + b;
      v0 = v0>0.f?v0:0.f; v1 = v1>0.f?v1:0.f;
      d_h1[(size_t)(i*128+m0)*LDH + col] = v0;
      d_h1[(size_t)(i*128+m0+1)*LDH + col] = v1;
    }
  }
}
__global__ void k_setpw1(const float* p) { if (threadIdx.x==0) d_pw1c = (float*)p; }

// ---------------- LSTM: cluster of 8 CTAs/direction, st.async + mbarrier ping-pong ----------------
__global__ void __launch_bounds__(400,1) k_lstm(const float* __restrict__ whhf,
                                                const float* __restrict__ whhb)
{
  int rank = blockIdx.x & 7, dir = blockIdx.x >> 3;
  const float* whh = dir ? whhb : whhf;
  const float* X = d_Xbuf + (size_t)dir * T_ * 800;
  int tid = threadIdx.x, gid = tid >> 2, quarter = tid & 3;
  int q = gid / 25, tloc = gid - q*25;
  int grow = q*200 + rank*25 + tloc;
  unsigned long long w2[25];
  {
    const unsigned long long* wp = (const unsigned long long*)(whh + (size_t)grow*200 + quarter*50);
#pragma unroll
    for (int j = 0; j < 25; j++) w2[j] = wp[j];
  }
  __shared__ __align__(16) float hbuf[2][208];
  __shared__ float gbuf[104];
  __shared__ __align__(8) unsigned long long mb[2];
  if (tid < 200) { hbuf[0][tid] = 0.f; }
  if (tid == 0) {
    asm volatile("mbarrier.init.shared.b64 [%0], 1;" :: "r"(s2u(&mb[0])) : "memory");
    asm volatile("mbarrier.init.shared.b64 [%0], 1;" :: "r"(s2u(&mb[1])) : "memory");
  }
  float c = 0.f;
  __syncthreads();
  csync();
  uint32_t mba0 = s2u(&mb[0]), mba1 = s2u(&mb[1]);
  uint32_t hb0 = s2u(&hbuf[0][0]), hb1 = s2u(&hbuf[1][0]);
  uint32_t ph0 = 0, ph1 = 0;
  for (int s = 0; s < T_; s++) {
    int tt = dir ? (T_-1-s) : s;
    int qq = s & 1;
    float x = 0.f;
    if (quarter == 0) x = X[(size_t)tt*800 + grow];
    if (s > 0) {
      uint32_t mba = qq ? mba1 : mba0;
      if (tid == 0)
        asm volatile("mbarrier.arrive.expect_tx.shared.b64 _, [%0], %1;" :: "r"(mba), "r"(800u) : "memory");
      mbar_wait(mba, qq ? ph1 : ph0);
      if (qq) ph1 ^= 1; else ph0 ^= 1;
    }
    const float* hb = hbuf[qq];
    unsigned long long acc2 = 0ull;
    const unsigned long long* hp = (const unsigned long long*)(hb + quarter*50);
#pragma unroll
    for (int jj = 0; jj < 25; jj++) fma2(acc2, w2[jj], hp[jj]);
    float2 av = unpk(acc2);
    float r = av.x + av.y;
    unsigned am = __activemask();
    r += __shfl_xor_sync(am, r, 1);
    r += __shfl_xor_sync(am, r, 2);
    if (quarter == 0) gbuf[gid] = r + x;
    __syncthreads();
    if (tid < 25) {
      float ig = 1.f/(1.f+expf(-gbuf[tid]));
      float fg = 1.f/(1.f+expf(-gbuf[25+tid]));
      float gg = tanhf(gbuf[50+tid]);
      float og = 1.f/(1.f+expf(-gbuf[75+tid]));
      c = fg*c + ig*gg;
      float h = og * tanhf(c);
      int hg = rank*25 + tid;
      d_states[(size_t)tt*400 + dir*200 + hg] = h;
      if (s < T_-1) {
        uint32_t la = (qq ? hb0 : hb1) + hg*4u;
        uint32_t lm = qq ? mba0 : mba1;
        unsigned hv = __float_as_uint(h);
#pragma unroll
        for (int pe = 0; pe < 8; pe++) {
          asm volatile("{ .reg .b32 ra, rm; mapa.shared::cluster.u32 ra, %0, %2; mapa.shared::cluster.u32 rm, %1, %2; "
                       "st.async.shared::cluster.mbarrier::complete_tx::bytes.b32 [ra], %3, [rm]; }"
                       :: "r"(la), "r"(lm), "r"(pe), "r"(hv) : "memory");
        }
      }
    }
  }
  csync();
}

// ---------------- span feature build ----------------
__global__ void k_spang(const int* __restrict__ ss, const int* __restrict__ se,
                        const float* __restrict__ wemb)
{
  int sp = blockIdx.x, st = ss[sp], en = se[sp], width = en - st + 1;
  __shared__ float aw[10];
  int tid = threadIdx.x;
  if (tid < 10) {
    int ix = st + tid; if (ix > T_-1) ix = T_-1;
    aw[tid] = (tid < width) ? d_attns[ix] : -1e9f;
  }
  __syncthreads();
  float mx = aw[0];
#pragma unroll
  for (int w2 = 1; w2 < 10; w2++) mx = fmaxf(mx, aw[w2]);
  float wt[10], ssum = 0.f;
#pragma unroll
  for (int w2 = 0; w2 < 10; w2++) { float e = expf(aw[w2]-mx); wt[w2]=e; ssum+=e; }
  float inv = 1.f/ssum;
  float* grow = d_g + (size_t)sp*KG;
  for (int e = tid; e < 400; e += blockDim.x) {
    grow[e]     = d_states[(size_t)st*400 + e];
    grow[400+e] = d_states[(size_t)en*400 + e];
    float acc = 0.f;
#pragma unroll
    for (int w2 = 0; w2 < 10; w2++) {
      int ix = st + w2; if (ix > T_-1) ix = T_-1;
      acc += wt[w2] * d_embeds[(size_t)ix*E_ + e];
    }
    grow[800+e] = acc * inv;
  }
  if (tid < 20) grow[1200+tid] = wemb[binfn(width)*20 + tid];
}

// ---------------- exact top-k + positional stable sort ----------------
__global__ void __launch_bounds__(1024) k_topk(const int* __restrict__ ss, const int* __restrict__ se)
{
  int tid = threadIdx.x;
  unsigned long long key[20];
#pragma unroll
  for (int i = 0; i < 20; i++) {
    int idx = i*1024 + tid;
    unsigned u = __float_as_uint(d_si[idx]);
    u = (u & 0x80000000u) ? ~u : (u | 0x80000000u);
    key[i] = ((unsigned long long)u << 32) | (unsigned long long)(0xFFFFFFFFu - (unsigned)idx);
  }
  __shared__ int cnt, selc;
  __shared__ unsigned long long sel[512], sel2[512];
  unsigned long long lo = 0ull, hi = ~0ull;
  while (lo < hi) {
    unsigned long long mid = lo + ((hi-lo)>>1) + 1ull;
    if (tid == 0) cnt = 0;
    __syncthreads();
    int c = 0;
#pragma unroll
    for (int i = 0; i < 20; i++) c += (key[i] >= mid);
#pragma unroll
    for (int o = 16; o > 0; o >>= 1) c += __shfl_down_sync(0xffffffffu, c, o);
    if ((tid&31)==0) atomicAdd(&cnt, c);
    __syncthreads();
    int total = cnt;
    __syncthreads();
    if (total >= NK) lo = mid; else hi = mid - 1ull;
  }
  if (tid == 0) selc = 0;
  __syncthreads();
#pragma unroll
  for (int i = 0; i < 20; i++)
    if (key[i] >= lo) { int pp = atomicAdd(&selc, 1); if (pp < 512) sel[pp] = key[i]; }
  __syncthreads();
  if (tid < 512 && tid >= selc) sel[tid] = 0ull;
  __syncthreads();
  for (int ksz = 2; ksz <= 512; ksz <<= 1)
    for (int jsz = ksz>>1; jsz > 0; jsz >>= 1) {
      if (tid < 512) {
        int ixj = tid ^ jsz;
        if (ixj > tid) {
          bool asc = ((tid & ksz) == 0);
          unsigned long long a = sel[tid], b = sel[ixj];
          if ((a > b) == asc) { sel[tid]=b; sel[ixj]=a; }
        }
      }
      __syncthreads();
    }
  if (tid < 512) {
    if (tid < NK) {
      unsigned long long kk = sel[511 - tid];
      unsigned idx = 0xFFFFFFFFu - (unsigned)(kk & 0xFFFFFFFFull);
      unsigned st = (unsigned)ss[idx], en = (unsigned)se[idx];
      unsigned long long pos = (unsigned long long)(st*2049u + en);
      sel2[tid] = (pos << 24) | ((unsigned long long)tid << 15) | (unsigned long long)idx;
    } else sel2[tid] = ~0ull;
  }
  __syncthreads();
  for (int ksz = 2; ksz <= 512; ksz <<= 1)
    for (int jsz = ksz>>1; jsz > 0; jsz >>= 1) {
      if (tid < 512) {
        int ixj = tid ^ jsz;
        if (ixj > tid) {
          bool asc = ((tid & ksz) == 0);
          unsigned long long a = sel2[tid], b = sel2[ixj];
          if ((a > b) == asc) { sel2[tid]=b; sel2[ixj]=a; }
        }
      }
      __syncthreads();
    }
  if (tid < NK) {
    int idx = (int)(sel2[tid] & 0x7FFFull);
    d_keep[tid] = idx; d_sk[tid] = d_si[idx];
    d_stk[tid] = ss[idx]; d_enk[tid] = se[idx];
  }
}

__global__ void k_gather() {
  int i = blockIdx.x, src = d_keep[i];
  float4* d = (float4*)(d_gk + (size_t)i*KG);
  const float4* s = (const float4*)(d_g + (size_t)src*KG);
  for (int k = threadIdx.x; k < KG/4; k += blockDim.x) d[k] = s[k];
}

__global__ void k_zeroAB() {
  int idx = threadIdx.x + blockIdx.x*blockDim.x;
  if (idx < NK*150) { d_Ai[idx] = 0.f; d_Bj[idx] = 0.f; }
}

__global__ void __launch_bounds__(160) k_abgemm(const float* __restrict__ pw1) {
  __shared__ float As2[244][32];
  int rb = blockIdx.x, yz = blockIdx.y;
  int mat = yz / 5, ks5 = yz % 5;
  const float* W = pw1 + mat*1220;
  float* O = mat ? d_Bj : d_Ai;
  int k0 = ks5*244;
  int tid = threadIdx.x;
  for (int idx = tid; idx < 244*32; idx += 160) {
    int k = idx >> 5, r = idx & 31;
    As2[k][r] = d_gk[(size_t)(rb*32+r)*KG + k0 + k];
  }
  __syncthreads();
  int col = tid;
  float acc[32];
#pragma unroll
  for (int r = 0; r < 32; r++) acc[r] = 0.f;
  if (col < 150) {
    const float* wr = W + (size_t)col*3680 + k0;
    for (int k = 0; k < 244; k++) {
      float w = wr[k];
      const float4* ar = (const float4*)As2[k];
#pragma unroll
      for (int r4 = 0; r4 < 8; r4++) {
        float4 a = ar[r4];
        acc[r4*4+0] += a.x*w; acc[r4*4+1] += a.y*w;
        acc[r4*4+2] += a.z*w; acc[r4*4+3] += a.w*w;
      }
    }
#pragma unroll
    for (int r = 0; r < 32; r++) atomicAdd(&O[(rb*32+r)*150 + col], acc[r]);
  }
}

__global__ void k_dist(const float* __restrict__ pw1, const float* __restrict__ demb) {
  int idx = threadIdx.x + blockIdx.x*blockDim.x;
  if (idx < 9*150) {
    int b = idx/150, n = idx - b*150;
    float acc = 0.f;
#pragma unroll
    for (int f = 0; f < 20; f++) acc += pw1[(size_t)n*3680 + 3660 + f] * demb[b*20+f];
    d_Dd[b*150+n] = acc;
  }
}

__global__ void k_final(float* __restrict__ out) {
  int i = blockIdx.x, a = threadIdx.x;
  if (a < 128) {
    int j = i - 1 - a; int jc = j < 0 ? 0 : (j > NK-1 ? NK-1 : j);
    float v = (j >= 0) ? d_sk[i] + d_sk[jc] + d_ps[i*NA + a] : -1e9f;
    out[i*129 + a] = v;
  } else if (a == 128) out[i*129 + 128] = 0.f;
}

static inline dim3 gg(int M, int N) { return dim3((M+127)/128, (N+159)/160); }

extern "C" void kernel_launch(void* const* d_in, const int* in_sizes, int n_in,
                              void* d_out, int out_size) {
  const int* tok = (const int*)d_in[0];
  const int* ss  = (const int*)d_in[1];
  const int* se  = (const int*)d_in[2];
  const float* emb   = (const float*)d_in[3];
  const float* wih_f = (const float*)d_in[4];
  const float* whh_f = (const float*)d_in[5];
  const float* b_f   = (const float*)d_in[6];
  const float* wih_b = (const float*)d_in[7];
  const float* whh_b = (const float*)d_in[8];
  const float* b_b   = (const float*)d_in[9];
  const float* aw1 = (const float*)d_in[10]; const float* ab1 = (const float*)d_in[11];
  const float* aw2 = (const float*)d_in[12]; const float* ab2 = (const float*)d_in[13];
  const float* aw3 = (const float*)d_in[14]; const float* ab3 = (const float*)d_in[15];
  const float* wemb = (const float*)d_in[16];
  const float* mw1 = (const float*)d_in[17]; const float* mb1 = (const float*)d_in[18];
  const float* mw2 = (const float*)d_in[19]; const float* mb2 = (const float*)d_in[20];
  const float* mw3 = (const float*)d_in[21]; const float* mb3 = (const float*)d_in[22];
  const float* demb = (const float*)d_in[23];
  const float* pw1 = (const float*)d_in[24]; const float* pb1 = (const float*)d_in[25];
  const float* pw2 = (const float*)d_in[26]; const float* pb2 = (const float*)d_in[27];
  const float* pw3 = (const float*)d_in[28]; const float* pb3 = (const float*)d_in[29];
  float* out = (float*)d_out;

  static int attr_done = 0;
  if (!attr_done) {
    cudaFuncSetAttribute(k_gemm, cudaFuncAttributeMaxDynamicSharedMemorySize, GEMM_SMEM);
    cudaFuncSetAttribute(k_pgemm, cudaFuncAttributeMaxDynamicSharedMemorySize, GEMM_SMEM);
    attr_done = 1;
  }

  float* Xf; float* states; float* h1; float* g; float* attns; float* si; float* ps;
  float* embeds;
  cudaGetSymbolAddress((void**)&Xf, d_Xbuf);
  cudaGetSymbolAddress((void**)&states, d_states);
  cudaGetSymbolAddress((void**)&h1, d_h1);
  cudaGetSymbolAddress((void**)&g, d_g);
  cudaGetSymbolAddress((void**)&attns, d_attns);
  cudaGetSymbolAddress((void**)&si, d_si);
  cudaGetSymbolAddress((void**)&ps, d_ps);
  cudaGetSymbolAddress((void**)&embeds, d_embeds);

  k_setpw1<<<1,32>>>(pw1);
  k_embed<<<T_, 128>>>(tok, emb);
  k_gemm<<<gg(T_,800), 256, GEMM_SMEM>>>(embeds, wih_f, b_f, Xf,          T_, 800, 400, 400, 400, 800, 0, 0, 0, 0);
  k_gemm<<<gg(T_,800), 256, GEMM_SMEM>>>(embeds, wih_b, b_b, Xf + T_*800, T_, 800, 400, 400, 400, 800, 0, 0, 0, 0);

  {
    cudaLaunchConfig_t cfg = {};
    cfg.gridDim = dim3(16,1,1); cfg.blockDim = dim3(400,1,1);
    cudaLaunchAttribute attr[1];
    attr[0].id = cudaLaunchAttributeClusterDimension;
    attr[0].val.clusterDim.x = 8; attr[0].val.clusterDim.y = 1; attr[0].val.clusterDim.z = 1;
    cfg.attrs = attr; cfg.numAttrs = 1; cfg.stream = 0;
    cudaLaunchKernelEx(&cfg, k_lstm, whh_f, whh_b);
  }

  // attention MLP over tokens (layer2 fused with w3 dot)
  k_gemm<<<gg(T_,150), 256, GEMM_SMEM>>>(states, aw1, ab1, h1, T_, 150, 400, 400, 400, LDH, 1, 0, 0, 0);
  k_gemm<<<gg(T_,150), 256, GEMM_SMEM>>>(h1, aw2, ab2, 0,     T_, 150, 150, LDH, 150, 0, 1, aw3, ab3, attns);

  k_spang<<<NS, 128>>>(ss, se, wemb);

  // mention MLP
  k_gemm<<<gg(NS,150), 256, GEMM_SMEM>>>(g, mw1, mb1, h1, NS, 150, KG, KG, KG, LDH, 1, 0, 0, 0);
  k_gemm<<<gg(NS,150), 256, GEMM_SMEM>>>(h1, mw2, mb2, 0, NS, 150, 150, LDH, 150, 0, 1, mw3, mb3, si);

  k_topk<<<1, 1024>>>(ss, se);
  k_gather<<<NK, 128>>>();

  // pair MLP (decomposed + fused)
  k_zeroAB<<<(NK*150+255)/256, 256>>>();
  k_abgemm<<<dim3(NK/32, 10), 160>>>(pw1);
  k_dist<<<6, 256>>>(pw1, demb);
  k_pgemm<<<NK, 256, GEMM_SMEM>>>(pb1);
  k_gemm<<<gg(NP,150), 256, GEMM_SMEM>>>(h1, pw2, pb2, 0, NP, 150, 150, LDH, 150, 0, 1, pw3, pb3, ps);

  k_final<<<NK, 160>>>(out);
}